// round 3
// baseline (speedup 1.0000x reference)
#include <cuda_runtime.h>

// Problem dims (fixed by the dataset)
#define ZD 96
#define YD 96
#define XD 96
#define PL 9216               // YD*XD
#define VOL 884736            // ZD*PL
#define CH 4
#define KW 7

// Tiling
#define TX 32
#define TY 8
#define NT 256                // TX*TY
#define ZSEG 16
#define NZSEG 6               // 96/ZSEG
#define XH 38                 // TX+6
#define SH 14                 // TY+6
#define SW 40                 // padded row stride

// ---------------- persistent device scratch ----------------
__device__ float g_wlif[CH][KW];
__device__ float g_wq[CH][KW];
__device__ float g_slif[CH][ZD];   // partial sums of wlif (conv_ones factor)
__device__ float g_sq[CH][ZD];     // partial sums of wq   (for q identity)
__device__ int   g_same;           // sigma2 == sigma3 ?
__device__ float g_u[CH * VOL];    // current u
__device__ float g_bufA[3 * CH * VOL];  // [0..3]=Cn [4..7]=Cn^2 [8..11]=C2q
__device__ float g_bufB[CH * VOL];      // logits

// ---------------- setup ----------------
__global__ void k_setup(const float* __restrict__ sigma2,
                        const float* __restrict__ sigma3) {
    int c = threadIdx.x;
    if (c == 0) {
        int s = 1;
        for (int k = 0; k < CH; k++) s &= (sigma2[k] == sigma3[k]);
        g_same = s;
    }
    if (c < CH) {
        float s2 = sigma2[c], s3 = sigma3[c];
        float w2[KW], w3[KW];
        float sum2 = 0.f, sum3 = 0.f;
        for (int t = 0; t < KW; t++) {
            float d = (float)(t - 3);
            w2[t] = expf(-d * d / (2.f * s2 * s2)); sum2 += w2[t];
            w3[t] = expf(-d * d / (2.f * s3 * s3)); sum3 += w3[t];
        }
        for (int t = 0; t < KW; t++) {
            g_wq[c][t]   = w2[t] / sum2;
            g_wlif[c][t] = w3[t] / sum3;
        }
        for (int p = 0; p < ZD; p++) {
            float sl = 0.f, sq = 0.f;
            for (int t = 0; t < KW; t++) {
                int q = p + t - 3;
                if (q >= 0 && q < ZD) { sl += g_wlif[c][t]; sq += g_wq[c][t]; }
            }
            g_slif[c][p] = sl;
            g_sq[c][p]   = sq;
        }
    }
}

// ---------------- u0 = softmax(o / eta) ----------------
__global__ void k_init(const float* __restrict__ o,
                       const float* __restrict__ eta_p) {
    int i = blockIdx.x * blockDim.x + threadIdx.x;
    if (i >= VOL) return;
    float inv_eta = 1.f / eta_p[0];
    float a0 = o[i] * inv_eta;
    float a1 = o[VOL + i] * inv_eta;
    float a2 = o[2 * VOL + i] * inv_eta;
    float a3 = o[3 * VOL + i] * inv_eta;
    float m = fmaxf(fmaxf(a0, a1), fmaxf(a2, a3));
    float e0 = expf(a0 - m), e1 = expf(a1 - m), e2 = expf(a2 - m), e3 = expf(a3 - m);
    float inv = 1.f / (e0 + e1 + e2 + e3);
    g_u[i] = e0 * inv;
    g_u[VOL + i] = e1 * inv;
    g_u[2 * VOL + i] = e2 * inv;
    g_u[3 * VOL + i] = e3 * inv;
}

// ============ Kernel A: u,I -> Cn, Cn^2, C2q (fused separable 3D convs) ============
__global__ __launch_bounds__(NT, 4) void kA(const float* __restrict__ I) {
    const int bz = blockIdx.z;
    const int c  = bz / NZSEG;
    const int zs = (bz - c * NZSEG) * ZSEG;
    const int x0 = blockIdx.x * TX;
    const int y0 = blockIdx.y * TY;

    __shared__ float s0[SH][SW], s1[SH][SW];              // raw: u*I, u
    __shared__ float t0[TY][SW], t1[TY][SW], t2[TY][SW];  // y-conv: wl(uI), wl(u), wq(u)

    const int tid = threadIdx.x;
    const int tx = tid & (TX - 1);
    const int ty = tid >> 5;
    const int same = g_same;

    float wl[KW], wq[KW];
#pragma unroll
    for (int t = 0; t < KW; t++) { wl[t] = g_wlif[c][t]; wq[t] = g_wq[c][t]; }

    // z-invariant smem-load addressing (3 slots: ceil(532/256))
    int l_soff[3], l_goff[3];
#pragma unroll
    for (int k = 0; k < 3; k++) {
        int idx = tid + k * NT;
        l_goff[k] = -1; l_soff[k] = 0;
        if (idx < SH * XH) {
            int yy = idx / XH;
            int xh = idx - yy * XH;
            int gy = y0 + yy - 3;
            int gx = x0 + xh - 3;
            l_soff[k] = yy * SW + xh;
            if (gy >= 0 && gy < YD && gx >= 0 && gx < XD)
                l_goff[k] = gy * XD + gx;
        } else {
            l_soff[k] = -1;
        }
    }
    // z-invariant y-conv addressing (2 slots: ceil(304/256))
    int y_yo[2], y_xh[2];
#pragma unroll
    for (int k = 0; k < 2; k++) {
        int idx = tid + k * NT;
        if (idx < TY * XH) { y_yo[k] = idx / XH; y_xh[k] = idx - y_yo[k] * XH; }
        else { y_yo[k] = -1; y_xh[k] = 0; }
    }

    const int out_xy = (y0 + ty) * XD + (x0 + tx);
    const float* uC = g_u + c * VOL;

    float r0[KW], r1[KW], r2[KW];
#pragma unroll
    for (int t = 0; t < KW; t++) { r0[t] = 0.f; r1[t] = 0.f; r2[t] = 0.f; }

    for (int s = zs - 3; s < zs + ZSEG + 3; ++s) {
#pragma unroll
        for (int t = 0; t < KW - 1; t++) { r0[t] = r0[t+1]; r1[t] = r1[t+1]; r2[t] = r2[t+1]; }

        if (s >= 0 && s < ZD) {
            const int sp = s * PL;
#pragma unroll
            for (int k = 0; k < 3; k++) {
                if (l_soff[k] >= 0) {
                    float uv = 0.f, Iv = 0.f;
                    if (l_goff[k] >= 0) {
                        uv = uC[sp + l_goff[k]];
                        Iv = I[sp + l_goff[k]];
                    }
                    *((&s0[0][0]) + l_soff[k]) = uv * Iv;
                    *((&s1[0][0]) + l_soff[k]) = uv;
                }
            }
            __syncthreads();
#pragma unroll
            for (int k = 0; k < 2; k++) {
                if (y_yo[k] >= 0) {
                    int yo = y_yo[k], xh = y_xh[k];
                    float a0 = 0.f, a1 = 0.f, a2 = 0.f;
#pragma unroll
                    for (int t = 0; t < KW; t++) {
                        a0 += wl[t] * s0[yo + t][xh];
                        a1 += wl[t] * s1[yo + t][xh];
                    }
                    if (!same) {
#pragma unroll
                        for (int t = 0; t < KW; t++) a2 += wq[t] * s1[yo + t][xh];
                    }
                    t0[yo][xh] = a0; t1[yo][xh] = a1; t2[yo][xh] = a2;
                }
            }
            __syncthreads();
            float v0 = 0.f, v1 = 0.f, v2 = 0.f;
#pragma unroll
            for (int t = 0; t < KW; t++) {
                v0 += wl[t] * t0[ty][tx + t];
                v1 += wl[t] * t1[ty][tx + t];
            }
            if (!same) {
#pragma unroll
                for (int t = 0; t < KW; t++) v2 += wq[t] * t2[ty][tx + t];
            }
            r0[KW-1] = v0; r1[KW-1] = v1; r2[KW-1] = v2;
        } else {
            r0[KW-1] = 0.f; r1[KW-1] = 0.f; r2[KW-1] = 0.f;
        }

        if (s >= zs + 3) {
            int z = s - 3;
            float C1 = 0.f, C2 = 0.f, C2q = 0.f;
#pragma unroll
            for (int t = 0; t < KW; t++) {
                C1 += wl[t] * r0[t];
                C2 += wl[t] * r1[t];
            }
            if (!same) {
#pragma unroll
                for (int t = 0; t < KW; t++) C2q += wq[t] * r2[t];
            } else {
                C2q = C2;
            }
            float Cn = (C1 + 1e-6f) / (C2 + 1e-6f);
            int i = z * PL + out_xy;
            g_bufA[(0 * CH + c) * VOL + i] = Cn;
            g_bufA[(1 * CH + c) * VOL + i] = Cn * Cn;
            g_bufA[(2 * CH + c) * VOL + i] = C2q;
        }
    }
}

// ============ Kernel B: Cn,Cn^2 -> conv -> Lif + q + o -> logits ============
__global__ __launch_bounds__(NT, 5) void kB(const float* __restrict__ o,
                                            const float* __restrict__ I,
                                            const float* __restrict__ lam_p,
                                            const float* __restrict__ mu_p) {
    const int bz = blockIdx.z;
    const int c  = bz / NZSEG;
    const int zs = (bz - c * NZSEG) * ZSEG;
    const int x0 = blockIdx.x * TX;
    const int y0 = blockIdx.y * TY;

    __shared__ float sE[SH][SW], sD[SH][SW];
    __shared__ float tE[TY][SW], tD[TY][SW];

    const int tid = threadIdx.x;
    const int tx = tid & (TX - 1);
    const int ty = tid >> 5;

    const float lam = lam_p[0];
    const float mu  = mu_p[0];

    float wl[KW];
#pragma unroll
    for (int t = 0; t < KW; t++) wl[t] = g_wlif[c][t];

    int l_soff[3], l_goff[3];
#pragma unroll
    for (int k = 0; k < 3; k++) {
        int idx = tid + k * NT;
        l_goff[k] = -1;
        if (idx < SH * XH) {
            int yy = idx / XH;
            int xh = idx - yy * XH;
            int gy = y0 + yy - 3;
            int gx = x0 + xh - 3;
            l_soff[k] = yy * SW + xh;
            if (gy >= 0 && gy < YD && gx >= 0 && gx < XD)
                l_goff[k] = gy * XD + gx;
        } else {
            l_soff[k] = -1;
        }
    }
    int y_yo[2], y_xh[2];
#pragma unroll
    for (int k = 0; k < 2; k++) {
        int idx = tid + k * NT;
        if (idx < TY * XH) { y_yo[k] = idx / XH; y_xh[k] = idx - y_yo[k] * XH; }
        else { y_yo[k] = -1; y_xh[k] = 0; }
    }

    const int out_xy = (y0 + ty) * XD + (x0 + tx);
    const float* bCn  = g_bufA + (0 * CH + c) * VOL;
    const float* bCn2 = g_bufA + (1 * CH + c) * VOL;
    const float* bC2q = g_bufA + (2 * CH + c) * VOL;

    const float sy = g_slif[c][y0 + ty];
    const float sx = g_slif[c][x0 + tx];
    const float qy = g_sq[c][y0 + ty];
    const float qx = g_sq[c][x0 + tx];

    float rE[KW], rD[KW];
#pragma unroll
    for (int t = 0; t < KW; t++) { rE[t] = 0.f; rD[t] = 0.f; }

    for (int s = zs - 3; s < zs + ZSEG + 3; ++s) {
#pragma unroll
        for (int t = 0; t < KW - 1; t++) { rE[t] = rE[t+1]; rD[t] = rD[t+1]; }

        if (s >= 0 && s < ZD) {
            const int sp = s * PL;
#pragma unroll
            for (int k = 0; k < 3; k++) {
                if (l_soff[k] >= 0) {
                    float e = 0.f, d = 0.f;
                    if (l_goff[k] >= 0) {
                        e = bCn[sp + l_goff[k]];
                        d = bCn2[sp + l_goff[k]];
                    }
                    *((&sE[0][0]) + l_soff[k]) = e;
                    *((&sD[0][0]) + l_soff[k]) = d;
                }
            }
            __syncthreads();
#pragma unroll
            for (int k = 0; k < 2; k++) {
                if (y_yo[k] >= 0) {
                    int yo = y_yo[k], xh = y_xh[k];
                    float aE = 0.f, aD = 0.f;
#pragma unroll
                    for (int t = 0; t < KW; t++) {
                        aE += wl[t] * sE[yo + t][xh];
                        aD += wl[t] * sD[yo + t][xh];
                    }
                    tE[yo][xh] = aE; tD[yo][xh] = aD;
                }
            }
            __syncthreads();
            float vE = 0.f, vD = 0.f;
#pragma unroll
            for (int t = 0; t < KW; t++) {
                vE += wl[t] * tE[ty][tx + t];
                vD += wl[t] * tD[ty][tx + t];
            }
            rE[KW-1] = vE; rD[KW-1] = vD;
        } else {
            rE[KW-1] = 0.f; rD[KW-1] = 0.f;
        }

        if (s >= zs + 3) {
            int z = s - 3;
            float E = 0.f, D = 0.f;
#pragma unroll
            for (int t = 0; t < KW; t++) { E += wl[t] * rE[t]; D += wl[t] * rD[t]; }
            int i = z * PL + out_xy;
            float Iv = I[i];
            float cones = g_slif[c][z] * sy * sx;
            float Lif = D - 2.f * Iv * E + Iv * Iv * cones;
            // q = conv_wq(1-2u) = Sq - 2*conv_wq(u)
            float q = g_sq[c][z] * qy * qx - 2.f * bC2q[i];
            g_bufB[c * VOL + i] = o[c * VOL + i] - mu * Lif - lam * q;
        }
    }
}

// ============ Kernel C: softmax(logits / eta) ============
__global__ void kC(const float* __restrict__ eta_p, float* __restrict__ out,
                   int write_ext) {
    int i = blockIdx.x * blockDim.x + threadIdx.x;
    if (i >= VOL) return;
    float inv_eta = 1.f / eta_p[0];
    float a0 = g_bufB[i] * inv_eta;
    float a1 = g_bufB[VOL + i] * inv_eta;
    float a2 = g_bufB[2 * VOL + i] * inv_eta;
    float a3 = g_bufB[3 * VOL + i] * inv_eta;
    float m = fmaxf(fmaxf(a0, a1), fmaxf(a2, a3));
    float e0 = expf(a0 - m), e1 = expf(a1 - m), e2 = expf(a2 - m), e3 = expf(a3 - m);
    float inv = 1.f / (e0 + e1 + e2 + e3);
    float* dst = write_ext ? out : g_u;
    dst[i] = e0 * inv;
    dst[VOL + i] = e1 * inv;
    dst[2 * VOL + i] = e2 * inv;
    dst[3 * VOL + i] = e3 * inv;
}

// ---------------- launch ----------------
extern "C" void kernel_launch(void* const* d_in, const int* in_sizes, int n_in,
                              void* d_out, int out_size) {
    const float* o      = (const float*)d_in[0];
    const float* I      = (const float*)d_in[1];
    const float* sigma2 = (const float*)d_in[2];
    const float* sigma3 = (const float*)d_in[3];
    const float* eta    = (const float*)d_in[4];
    const float* lam    = (const float*)d_in[5];
    const float* mu     = (const float*)d_in[6];
    float* out = (float*)d_out;

    const int Tpt = 256;
    const int Bpt = (VOL + Tpt - 1) / Tpt;

    k_setup<<<1, 32>>>(sigma2, sigma3);
    k_init<<<Bpt, Tpt>>>(o, eta);

    dim3 grid(XD / TX, YD / TY, CH * NZSEG);  // (3, 12, 24) = 864 blocks

    const int NB_ITERS = 10;
    for (int it = 0; it < NB_ITERS; ++it) {
        kA<<<grid, NT>>>(I);
        kB<<<grid, NT>>>(o, I, lam, mu);
        kC<<<Bpt, Tpt>>>(eta, out, (it == NB_ITERS - 1) ? 1 : 0);
    }
}

// round 4
// speedup vs baseline: 1.3340x; 1.3340x over previous
#include <cuda_runtime.h>

// Problem dims (fixed by the dataset)
#define ZD 96
#define YD 96
#define XD 96
#define PL 9216               // YD*XD
#define VOL 884736            // ZD*PL
#define CH 4
#define KW 7
#define SEG 12
#define NSEG 8                // 96/SEG

// ---------------- persistent device scratch ----------------
__device__ float g_wlif[CH][KW];
__device__ float g_wq[CH][KW];
__device__ float g_slif[CH][ZD];   // partial sums of wlif (conv_ones factor)
__device__ float g_sq[CH][ZD];     // partial sums of wq   (q identity factor)
__device__ int   g_same;           // sigma2 == sigma3 ?
__device__ float g_u[CH * VOL];        // current u
__device__ float g_bufA[3 * CH * VOL]; // p1 out / p3 out
__device__ float g_bufB[3 * CH * VOL]; // p2 out / p4 logits

// ---------------- setup ----------------
__global__ void k_setup(const float* __restrict__ sigma2,
                        const float* __restrict__ sigma3) {
    int c = threadIdx.x;
    if (c == 0) {
        int s = 1;
        for (int k = 0; k < CH; k++) s &= (sigma2[k] == sigma3[k]);
        g_same = s;
    }
    if (c < CH) {
        float s2 = sigma2[c], s3 = sigma3[c];
        float w2[KW], w3[KW];
        float sum2 = 0.f, sum3 = 0.f;
        for (int t = 0; t < KW; t++) {
            float d = (float)(t - 3);
            w2[t] = expf(-d * d / (2.f * s2 * s2)); sum2 += w2[t];
            w3[t] = expf(-d * d / (2.f * s3 * s3)); sum3 += w3[t];
        }
        for (int t = 0; t < KW; t++) {
            g_wq[c][t]   = w2[t] / sum2;
            g_wlif[c][t] = w3[t] / sum3;
        }
        for (int p = 0; p < ZD; p++) {
            float sl = 0.f, sq = 0.f;
            for (int t = 0; t < KW; t++) {
                int q = p + t - 3;
                if (q >= 0 && q < ZD) { sl += g_wlif[c][t]; sq += g_wq[c][t]; }
            }
            g_slif[c][p] = sl;
            g_sq[c][p]   = sq;
        }
    }
}

// ---------------- u0 = softmax(o / eta) ----------------
__global__ void k_init(const float* __restrict__ o,
                       const float* __restrict__ eta_p) {
    int i = blockIdx.x * blockDim.x + threadIdx.x;
    if (i >= VOL) return;
    float inv_eta = 1.f / eta_p[0];
    float a0 = o[i] * inv_eta;
    float a1 = o[VOL + i] * inv_eta;
    float a2 = o[2 * VOL + i] * inv_eta;
    float a3 = o[3 * VOL + i] * inv_eta;
    float m = fmaxf(fmaxf(a0, a1), fmaxf(a2, a3));
    float e0 = expf(a0 - m), e1 = expf(a1 - m), e2 = expf(a2 - m), e3 = expf(a3 - m);
    float inv = 1.f / (e0 + e1 + e2 + e3);
    g_u[i] = e0 * inv;
    g_u[VOL + i] = e1 * inv;
    g_u[2 * VOL + i] = e2 * inv;
    g_u[3 * VOL + i] = e3 * inv;
}

// ============ p1: z-ring conv of {u*I, u} (and wq(u) if sigmas differ) ============
// grid (3, 12, NSEG*CH), block (32, 8)
__global__ __launch_bounds__(256) void p1(const float* __restrict__ I) {
    const int x = blockIdx.x * 32 + threadIdx.x;
    const int y = blockIdx.y * 8 + threadIdx.y;
    const int bz = blockIdx.z;
    const int c  = bz >> 3;
    const int zs = (bz & 7) * SEG;
    const int xy = y * XD + x;
    const int same = g_same;

    float wl[KW], wq[KW];
#pragma unroll
    for (int t = 0; t < KW; t++) { wl[t] = g_wlif[c][t]; wq[t] = g_wq[c][t]; }

    const float* uC = g_u + c * VOL;
    float rI[KW], rU[KW];
#pragma unroll
    for (int t = 0; t < KW; t++) { rI[t] = 0.f; rU[t] = 0.f; }

    for (int s = zs - 3; s < zs + SEG + 3; ++s) {
#pragma unroll
        for (int t = 0; t < KW - 1; t++) { rI[t] = rI[t + 1]; rU[t] = rU[t + 1]; }
        float uv = 0.f, Iv = 0.f;
        if (s >= 0 && s < ZD) { int gi = s * PL + xy; uv = uC[gi]; Iv = I[gi]; }
        rU[KW - 1] = uv;
        rI[KW - 1] = uv * Iv;
        if (s >= zs + 3) {
            int z = s - 3;
            float a0 = 0.f, a1 = 0.f;
#pragma unroll
            for (int t = 0; t < KW; t++) { a0 += wl[t] * rI[t]; a1 += wl[t] * rU[t]; }
            int oidx = z * PL + xy;
            g_bufA[(0 * CH + c) * VOL + oidx] = a0;
            g_bufA[(1 * CH + c) * VOL + oidx] = a1;
            if (!same) {
                float a2 = 0.f;
#pragma unroll
                for (int t = 0; t < KW; t++) a2 += wq[t] * rU[t];
                g_bufA[(2 * CH + c) * VOL + oidx] = a2;
            }
        }
    }
}

// ============ p2: y-ring conv over p1 streams: bufA -> bufB ============
// grid (3, 12, NSEG*CH), block (32, 8); thread fixed (x,z), walks y
__global__ __launch_bounds__(256) void p2() {
    const int x = blockIdx.x * 32 + threadIdx.x;
    const int z = blockIdx.y * 8 + threadIdx.y;
    const int bz = blockIdx.z;
    const int c  = bz >> 3;
    const int ys = (bz & 7) * SEG;
    const int zx = z * PL + x;
    const int same = g_same;

    float wl[KW], wq[KW];
#pragma unroll
    for (int t = 0; t < KW; t++) { wl[t] = g_wlif[c][t]; wq[t] = g_wq[c][t]; }

    const float* b0 = g_bufA + (0 * CH + c) * VOL;
    const float* b1 = g_bufA + (1 * CH + c) * VOL;
    const float* b2 = g_bufA + (2 * CH + c) * VOL;

    float r0[KW], r1[KW], r2[KW];
#pragma unroll
    for (int t = 0; t < KW; t++) { r0[t] = 0.f; r1[t] = 0.f; r2[t] = 0.f; }

    for (int s = ys - 3; s < ys + SEG + 3; ++s) {
#pragma unroll
        for (int t = 0; t < KW - 1; t++) { r0[t] = r0[t+1]; r1[t] = r1[t+1]; r2[t] = r2[t+1]; }
        float v0 = 0.f, v1 = 0.f, v2 = 0.f;
        if (s >= 0 && s < YD) {
            int gi = zx + s * XD;
            v0 = b0[gi]; v1 = b1[gi];
            if (!same) v2 = b2[gi];
        }
        r0[KW-1] = v0; r1[KW-1] = v1; r2[KW-1] = v2;
        if (s >= ys + 3) {
            int y = s - 3;
            int oidx = zx + y * XD;
            float a0 = 0.f, a1 = 0.f;
#pragma unroll
            for (int t = 0; t < KW; t++) { a0 += wl[t] * r0[t]; a1 += wl[t] * r1[t]; }
            g_bufB[(0 * CH + c) * VOL + oidx] = a0;
            g_bufB[(1 * CH + c) * VOL + oidx] = a1;
            if (!same) {
                float a2 = 0.f;
#pragma unroll
                for (int t = 0; t < KW; t++) a2 += wq[t] * r2[t];
                g_bufB[(2 * CH + c) * VOL + oidx] = a2;
            }
        }
    }
}

// ============ p3: inline x-conv + Cn + z-ring conv of {Cn, Cn^2}; writes C2q ============
// grid (3, 12, NSEG*CH), block (32, 8); thread fixed (x,y), walks z
__global__ __launch_bounds__(256) void p3() {
    const int x = blockIdx.x * 32 + threadIdx.x;
    const int y = blockIdx.y * 8 + threadIdx.y;
    const int bz = blockIdx.z;
    const int c  = bz >> 3;
    const int zs = (bz & 7) * SEG;
    const int xy = y * XD + x;
    const int same = g_same;

    float wl[KW], wq[KW];
#pragma unroll
    for (int t = 0; t < KW; t++) { wl[t] = g_wlif[c][t]; wq[t] = g_wq[c][t]; }

    bool pv[KW];
#pragma unroll
    for (int t = 0; t < KW; t++) { int xx = x + t - 3; pv[t] = (xx >= 0 && xx < XD); }

    const float* b0 = g_bufB + (0 * CH + c) * VOL;
    const float* b1 = g_bufB + (1 * CH + c) * VOL;
    const float* b2 = g_bufB + (2 * CH + c) * VOL;

    float rCn[KW], rC2[KW];
#pragma unroll
    for (int t = 0; t < KW; t++) { rCn[t] = 0.f; rC2[t] = 0.f; }

    for (int s = zs - 3; s < zs + SEG + 3; ++s) {
#pragma unroll
        for (int t = 0; t < KW - 1; t++) { rCn[t] = rCn[t+1]; rC2[t] = rC2[t+1]; }
        float Cv = 0.f, C2v = 0.f;
        if (s >= 0 && s < ZD) {
            int base = s * PL + y * XD + x;   // tap addr = base + (t-3)
            float B0 = 0.f, B1 = 0.f;
#pragma unroll
            for (int t = 0; t < KW; t++) {
                if (pv[t]) {
                    B0 += wl[t] * b0[base + t - 3];
                    B1 += wl[t] * b1[base + t - 3];
                }
            }
            float B2;
            if (!same) {
                B2 = 0.f;
#pragma unroll
                for (int t = 0; t < KW; t++)
                    if (pv[t]) B2 += wq[t] * b2[base + t - 3];
            } else {
                B2 = B1;
            }
            float Cn = (B0 + 1e-6f) / (B1 + 1e-6f);
            Cv = Cn; C2v = Cn * Cn;
            if (s >= zs && s < zs + SEG)
                g_bufA[(2 * CH + c) * VOL + s * PL + xy] = B2;  // C2q fully conv'd
        }
        rCn[KW-1] = Cv; rC2[KW-1] = C2v;
        if (s >= zs + 3) {
            int z = s - 3;
            float a0 = 0.f, a1 = 0.f;
#pragma unroll
            for (int t = 0; t < KW; t++) { a0 += wl[t] * rCn[t]; a1 += wl[t] * rC2[t]; }
            int oidx = z * PL + xy;
            g_bufA[(0 * CH + c) * VOL + oidx] = a0;
            g_bufA[(1 * CH + c) * VOL + oidx] = a1;
        }
    }
}

// ============ p4: inline x-conv + y-ring conv of {Cn,Cn^2} -> Lif + q -> logits ============
// grid (3, 12, NSEG*CH), block (32, 8); thread fixed (x,z), walks y
__global__ __launch_bounds__(256) void p4(const float* __restrict__ o,
                                          const float* __restrict__ I,
                                          const float* __restrict__ eta_p,
                                          const float* __restrict__ lam_p,
                                          const float* __restrict__ mu_p) {
    const int x = blockIdx.x * 32 + threadIdx.x;
    const int z = blockIdx.y * 8 + threadIdx.y;
    const int bz = blockIdx.z;
    const int c  = bz >> 3;
    const int ys = (bz & 7) * SEG;
    const int zx = z * PL + x;

    const float lam = lam_p[0];
    const float mu  = mu_p[0];
    const float inv_eta = 1.f / eta_p[0];

    float wl[KW];
#pragma unroll
    for (int t = 0; t < KW; t++) wl[t] = g_wlif[c][t];

    bool pv[KW];
#pragma unroll
    for (int t = 0; t < KW; t++) { int xx = x + t - 3; pv[t] = (xx >= 0 && xx < XD); }

    const float* bE = g_bufA + (0 * CH + c) * VOL;  // zconv(Cn)
    const float* bD = g_bufA + (1 * CH + c) * VOL;  // zconv(Cn^2)
    const float* bQ = g_bufA + (2 * CH + c) * VOL;  // C2q

    const float slx = g_slif[c][x];
    const float slz = g_slif[c][z];
    const float sqx = g_sq[c][x];
    const float sqz = g_sq[c][z];
    const float* oC = o + c * VOL;

    float rE[KW], rD[KW];
#pragma unroll
    for (int t = 0; t < KW; t++) { rE[t] = 0.f; rD[t] = 0.f; }

    for (int s = ys - 3; s < ys + SEG + 3; ++s) {
#pragma unroll
        for (int t = 0; t < KW - 1; t++) { rE[t] = rE[t+1]; rD[t] = rD[t+1]; }
        float vE = 0.f, vD = 0.f;
        if (s >= 0 && s < YD) {
            int base = zx + s * XD;   // tap addr = base + (t-3)
#pragma unroll
            for (int t = 0; t < KW; t++) {
                if (pv[t]) {
                    vE += wl[t] * bE[base + t - 3];
                    vD += wl[t] * bD[base + t - 3];
                }
            }
        }
        rE[KW-1] = vE; rD[KW-1] = vD;
        if (s >= ys + 3) {
            int y = s - 3;
            int i = zx + y * XD;
            float E = 0.f, D = 0.f;
#pragma unroll
            for (int t = 0; t < KW; t++) { E += wl[t] * rE[t]; D += wl[t] * rD[t]; }
            float Iv = I[i];
            float cones = slz * g_slif[c][y] * slx;
            float Lif = D - 2.f * Iv * E + Iv * Iv * cones;
            float q = sqz * g_sq[c][y] * sqx - 2.f * bQ[i];
            g_bufB[c * VOL + i] = (oC[i] - mu * Lif - lam * q) * inv_eta;
        }
    }
}

// ============ kC: softmax over channels ============
__global__ void kC(float* __restrict__ out, int write_ext) {
    int i = blockIdx.x * blockDim.x + threadIdx.x;
    if (i >= VOL) return;
    float a0 = g_bufB[i];
    float a1 = g_bufB[VOL + i];
    float a2 = g_bufB[2 * VOL + i];
    float a3 = g_bufB[3 * VOL + i];
    float m = fmaxf(fmaxf(a0, a1), fmaxf(a2, a3));
    float e0 = expf(a0 - m), e1 = expf(a1 - m), e2 = expf(a2 - m), e3 = expf(a3 - m);
    float inv = 1.f / (e0 + e1 + e2 + e3);
    float* dst = write_ext ? out : g_u;
    dst[i] = e0 * inv;
    dst[VOL + i] = e1 * inv;
    dst[2 * VOL + i] = e2 * inv;
    dst[3 * VOL + i] = e3 * inv;
}

// ---------------- launch ----------------
extern "C" void kernel_launch(void* const* d_in, const int* in_sizes, int n_in,
                              void* d_out, int out_size) {
    const float* o      = (const float*)d_in[0];
    const float* I      = (const float*)d_in[1];
    const float* sigma2 = (const float*)d_in[2];
    const float* sigma3 = (const float*)d_in[3];
    const float* eta    = (const float*)d_in[4];
    const float* lam    = (const float*)d_in[5];
    const float* mu     = (const float*)d_in[6];
    float* out = (float*)d_out;

    const int Tpt = 256;
    const int Bpt = (VOL + Tpt - 1) / Tpt;

    k_setup<<<1, 32>>>(sigma2, sigma3);
    k_init<<<Bpt, Tpt>>>(o, eta);

    dim3 blk(32, 8);
    dim3 grid(3, 12, NSEG * CH);   // 1152 blocks

    const int NB_ITERS = 10;
    for (int it = 0; it < NB_ITERS; ++it) {
        p1<<<grid, blk>>>(I);
        p2<<<grid, blk>>>();
        p3<<<grid, blk>>>();
        p4<<<grid, blk>>>(o, I, eta, lam, mu);
        kC<<<Bpt, Tpt>>>(out, (it == NB_ITERS - 1) ? 1 : 0);
    }
}

// round 5
// speedup vs baseline: 1.3600x; 1.0195x over previous
#include <cuda_runtime.h>

// Problem dims
#define ZD 96
#define YD 96
#define XD 96
#define PL 9216
#define VOL 884736
#define CH 4
#define KW 7

// Segment configs
#define SEG1 24
#define NSEG1 4
#define SEG2 16
#define NSEG2 6
#define SEG4 12
#define NSEG4 8

// ---------------- persistent device scratch ----------------
__device__ float g_wlif[CH][KW];
__device__ float g_wq[CH][KW];
__device__ float g_slif[CH][ZD];
__device__ float g_sq[CH][ZD];
__device__ int   g_same;
__device__ float g_u[CH * VOL];
__device__ float g_bufA[3 * CH * VOL];  // q1 out: zconv{uI,u,(wq:u)} ; q3 out: zconv{Cn,Cn2}
__device__ float g_bufB[3 * CH * VOL];  // q2 out: Cn, Cn2, C2q

// ---------------- setup ----------------
__global__ void k_setup(const float* __restrict__ sigma2,
                        const float* __restrict__ sigma3) {
    int c = threadIdx.x;
    if (c == 0) {
        int s = 1;
        for (int k = 0; k < CH; k++) s &= (sigma2[k] == sigma3[k]);
        g_same = s;
    }
    if (c < CH) {
        float s2 = sigma2[c], s3 = sigma3[c];
        float w2[KW], w3[KW];
        float sum2 = 0.f, sum3 = 0.f;
        for (int t = 0; t < KW; t++) {
            float d = (float)(t - 3);
            w2[t] = expf(-d * d / (2.f * s2 * s2)); sum2 += w2[t];
            w3[t] = expf(-d * d / (2.f * s3 * s3)); sum3 += w3[t];
        }
        for (int t = 0; t < KW; t++) {
            g_wq[c][t]   = w2[t] / sum2;
            g_wlif[c][t] = w3[t] / sum3;
        }
        for (int p = 0; p < ZD; p++) {
            float sl = 0.f, sq = 0.f;
            for (int t = 0; t < KW; t++) {
                int q = p + t - 3;
                if (q >= 0 && q < ZD) { sl += g_wlif[c][t]; sq += g_wq[c][t]; }
            }
            g_slif[c][p] = sl;
            g_sq[c][p]   = sq;
        }
    }
}

// ---------------- u0 = softmax(o / eta) ----------------
__global__ void k_init(const float* __restrict__ o,
                       const float* __restrict__ eta_p) {
    int i = blockIdx.x * blockDim.x + threadIdx.x;
    if (i >= VOL) return;
    float inv_eta = 1.f / eta_p[0];
    float a0 = o[i] * inv_eta;
    float a1 = o[VOL + i] * inv_eta;
    float a2 = o[2 * VOL + i] * inv_eta;
    float a3 = o[3 * VOL + i] * inv_eta;
    float m = fmaxf(fmaxf(a0, a1), fmaxf(a2, a3));
    float e0 = expf(a0 - m), e1 = expf(a1 - m), e2 = expf(a2 - m), e3 = expf(a3 - m);
    float inv = 1.f / (e0 + e1 + e2 + e3);
    g_u[i] = e0 * inv;
    g_u[VOL + i] = e1 * inv;
    g_u[2 * VOL + i] = e2 * inv;
    g_u[3 * VOL + i] = e3 * inv;
}

// ============ q1: z-ring conv of {u*I, u} (+ wq(u) if sigmas differ) ============
// grid (3, 12, NSEG1*CH), block (32,8); thread fixed (x,y), walks z
__global__ __launch_bounds__(256) void q1(const float* __restrict__ I) {
    const int x = blockIdx.x * 32 + threadIdx.x;
    const int y = blockIdx.y * 8 + threadIdx.y;
    const int bz = blockIdx.z;
    const int c  = bz / NSEG1;
    const int zs = (bz - c * NSEG1) * SEG1;
    const int xy = y * XD + x;
    const int same = g_same;

    float wl[KW], wq[KW];
#pragma unroll
    for (int t = 0; t < KW; t++) { wl[t] = g_wlif[c][t]; wq[t] = g_wq[c][t]; }

    const float* uC = g_u + c * VOL;
    float rI[KW], rU[KW];
#pragma unroll
    for (int t = 0; t < KW; t++) { rI[t] = 0.f; rU[t] = 0.f; }

    for (int s = zs - 3; s < zs + SEG1 + 3; ++s) {
#pragma unroll
        for (int t = 0; t < KW - 1; t++) { rI[t] = rI[t + 1]; rU[t] = rU[t + 1]; }
        float uv = 0.f, Iv = 0.f;
        if (s >= 0 && s < ZD) { int gi = s * PL + xy; uv = uC[gi]; Iv = I[gi]; }
        rU[KW - 1] = uv;
        rI[KW - 1] = uv * Iv;
        if (s >= zs + 3) {
            int z = s - 3;
            float a0 = 0.f, a1 = 0.f;
#pragma unroll
            for (int t = 0; t < KW; t++) { a0 += wl[t] * rI[t]; a1 += wl[t] * rU[t]; }
            int oidx = z * PL + xy;
            g_bufA[(0 * CH + c) * VOL + oidx] = a0;
            g_bufA[(1 * CH + c) * VOL + oidx] = a1;
            if (!same) {
                float a2 = 0.f;
#pragma unroll
                for (int t = 0; t < KW; t++) a2 += wq[t] * rU[t];
                g_bufA[(2 * CH + c) * VOL + oidx] = a2;
            }
        }
    }
}

// ============ q2: y-ring + inline x-taps -> Cn, Cn^2, C2q (full conv) ============
// grid (3, 12, NSEG2*CH), block (32,8); thread fixed (x,z), walks y
__global__ __launch_bounds__(256) void q2() {
    const int x = blockIdx.x * 32 + threadIdx.x;
    const int z = blockIdx.y * 8 + threadIdx.y;
    const int bz = blockIdx.z;
    const int c  = bz / NSEG2;
    const int ys = (bz - c * NSEG2) * SEG2;
    const int zx = z * PL + x;
    const int same = g_same;

    float wl[KW], wq[KW];
#pragma unroll
    for (int t = 0; t < KW; t++) { wl[t] = g_wlif[c][t]; wq[t] = g_wq[c][t]; }

    bool pv[KW];
#pragma unroll
    for (int t = 0; t < KW; t++) { int xx = x + t - 3; pv[t] = (xx >= 0 && xx < XD); }

    const float* b0 = g_bufA + (0 * CH + c) * VOL;
    const float* b1 = g_bufA + (1 * CH + c) * VOL;
    const float* b2 = g_bufA + (2 * CH + c) * VOL;

    float r0[KW], r1[KW], r2[KW];
#pragma unroll
    for (int t = 0; t < KW; t++) { r0[t] = 0.f; r1[t] = 0.f; r2[t] = 0.f; }

    for (int s = ys - 3; s < ys + SEG2 + 3; ++s) {
#pragma unroll
        for (int t = 0; t < KW - 1; t++) { r0[t] = r0[t+1]; r1[t] = r1[t+1]; r2[t] = r2[t+1]; }
        float v0 = 0.f, v1 = 0.f, v2 = 0.f;
        if (s >= 0 && s < YD) {
            int base = zx + s * XD;
#pragma unroll
            for (int t = 0; t < KW; t++) {
                if (pv[t]) {
                    v0 += wl[t] * b0[base + t - 3];
                    v1 += wl[t] * b1[base + t - 3];
                }
            }
            if (!same) {
#pragma unroll
                for (int t = 0; t < KW; t++)
                    if (pv[t]) v2 += wq[t] * b2[base + t - 3];
            }
        }
        r0[KW-1] = v0; r1[KW-1] = v1; r2[KW-1] = v2;
        if (s >= ys + 3) {
            int y = s - 3;
            int oidx = zx + y * XD;
            float C1 = 0.f, C2 = 0.f;
#pragma unroll
            for (int t = 0; t < KW; t++) { C1 += wl[t] * r0[t]; C2 += wl[t] * r1[t]; }
            float C2q;
            if (!same) {
                C2q = 0.f;
#pragma unroll
                for (int t = 0; t < KW; t++) C2q += wq[t] * r2[t];
            } else {
                C2q = C2;
            }
            float Cn = (C1 + 1e-6f) / (C2 + 1e-6f);
            g_bufB[(0 * CH + c) * VOL + oidx] = Cn;
            g_bufB[(1 * CH + c) * VOL + oidx] = Cn * Cn;
            g_bufB[(2 * CH + c) * VOL + oidx] = C2q;
        }
    }
}

// ============ q3: z-ring pointwise conv of {Cn, Cn^2} ============
// grid (3, 12, NSEG2*CH), block (32,8); thread fixed (x,y), walks z
__global__ __launch_bounds__(256) void q3() {
    const int x = blockIdx.x * 32 + threadIdx.x;
    const int y = blockIdx.y * 8 + threadIdx.y;
    const int bz = blockIdx.z;
    const int c  = bz / NSEG2;
    const int zs = (bz - c * NSEG2) * SEG2;
    const int xy = y * XD + x;

    float wl[KW];
#pragma unroll
    for (int t = 0; t < KW; t++) wl[t] = g_wlif[c][t];

    const float* b0 = g_bufB + (0 * CH + c) * VOL;
    const float* b1 = g_bufB + (1 * CH + c) * VOL;

    float r0[KW], r1[KW];
#pragma unroll
    for (int t = 0; t < KW; t++) { r0[t] = 0.f; r1[t] = 0.f; }

    for (int s = zs - 3; s < zs + SEG2 + 3; ++s) {
#pragma unroll
        for (int t = 0; t < KW - 1; t++) { r0[t] = r0[t+1]; r1[t] = r1[t+1]; }
        float v0 = 0.f, v1 = 0.f;
        if (s >= 0 && s < ZD) { int gi = s * PL + xy; v0 = b0[gi]; v1 = b1[gi]; }
        r0[KW-1] = v0; r1[KW-1] = v1;
        if (s >= zs + 3) {
            int z = s - 3;
            float a0 = 0.f, a1 = 0.f;
#pragma unroll
            for (int t = 0; t < KW; t++) { a0 += wl[t] * r0[t]; a1 += wl[t] * r1[t]; }
            int oidx = z * PL + xy;
            g_bufA[(0 * CH + c) * VOL + oidx] = a0;
            g_bufA[(1 * CH + c) * VOL + oidx] = a1;
        }
    }
}

// ============ q4: y-ring + inline x-taps, ALL channels, Lif + q + softmax ============
// grid (3, 12, NSEG4), block (32,8); thread fixed (x,z), walks y
__global__ __launch_bounds__(256, 2) void q4(const float* __restrict__ o,
                                             const float* __restrict__ I,
                                             const float* __restrict__ eta_p,
                                             const float* __restrict__ lam_p,
                                             const float* __restrict__ mu_p,
                                             float* __restrict__ out,
                                             int write_ext) {
    const int x = blockIdx.x * 32 + threadIdx.x;
    const int z = blockIdx.y * 8 + threadIdx.y;
    const int ys = blockIdx.z * SEG4;
    const int zx = z * PL + x;

    const float lam = lam_p[0];
    const float mu  = mu_p[0];
    const float inv_eta = 1.f / eta_p[0];

    float wl[CH][KW];
#pragma unroll
    for (int c = 0; c < CH; c++)
#pragma unroll
        for (int t = 0; t < KW; t++) wl[c][t] = g_wlif[c][t];

    bool pv[KW];
#pragma unroll
    for (int t = 0; t < KW; t++) { int xx = x + t - 3; pv[t] = (xx >= 0 && xx < XD); }

    float slxz[CH], sqxz[CH];
#pragma unroll
    for (int c = 0; c < CH; c++) {
        slxz[c] = g_slif[c][x] * g_slif[c][z];
        sqxz[c] = g_sq[c][x] * g_sq[c][z];
    }

    float rE[CH][KW], rD[CH][KW];
#pragma unroll
    for (int c = 0; c < CH; c++)
#pragma unroll
        for (int t = 0; t < KW; t++) { rE[c][t] = 0.f; rD[c][t] = 0.f; }

    float* dst = write_ext ? out : g_u;

    for (int s = ys - 3; s < ys + SEG4 + 3; ++s) {
#pragma unroll
        for (int c = 0; c < CH; c++)
#pragma unroll
            for (int t = 0; t < KW - 1; t++) { rE[c][t] = rE[c][t+1]; rD[c][t] = rD[c][t+1]; }

        if (s >= 0 && s < YD) {
            int base = zx + s * XD;
#pragma unroll
            for (int c = 0; c < CH; c++) {
                const float* bE = g_bufA + (0 * CH + c) * VOL;
                const float* bD = g_bufA + (1 * CH + c) * VOL;
                float vE = 0.f, vD = 0.f;
#pragma unroll
                for (int t = 0; t < KW; t++) {
                    if (pv[t]) {
                        vE += wl[c][t] * bE[base + t - 3];
                        vD += wl[c][t] * bD[base + t - 3];
                    }
                }
                rE[c][KW-1] = vE; rD[c][KW-1] = vD;
            }
        } else {
#pragma unroll
            for (int c = 0; c < CH; c++) { rE[c][KW-1] = 0.f; rD[c][KW-1] = 0.f; }
        }

        if (s >= ys + 3) {
            int y = s - 3;
            int i = zx + y * XD;
            float Iv = I[i];
            float a[CH];
#pragma unroll
            for (int c = 0; c < CH; c++) {
                float E = 0.f, D = 0.f;
#pragma unroll
                for (int t = 0; t < KW; t++) { E += wl[c][t] * rE[c][t]; D += wl[c][t] * rD[c][t]; }
                float cones = slxz[c] * g_slif[c][y];
                float Lif = D - 2.f * Iv * E + Iv * Iv * cones;
                float q = sqxz[c] * g_sq[c][y] - 2.f * g_bufB[(2 * CH + c) * VOL + i];
                a[c] = (o[c * VOL + i] - mu * Lif - lam * q) * inv_eta;
            }
            float m = fmaxf(fmaxf(a[0], a[1]), fmaxf(a[2], a[3]));
            float e0 = expf(a[0] - m), e1 = expf(a[1] - m);
            float e2 = expf(a[2] - m), e3 = expf(a[3] - m);
            float inv = 1.f / (e0 + e1 + e2 + e3);
            dst[i] = e0 * inv;
            dst[VOL + i] = e1 * inv;
            dst[2 * VOL + i] = e2 * inv;
            dst[3 * VOL + i] = e3 * inv;
        }
    }
}

// ---------------- launch ----------------
extern "C" void kernel_launch(void* const* d_in, const int* in_sizes, int n_in,
                              void* d_out, int out_size) {
    const float* o      = (const float*)d_in[0];
    const float* I      = (const float*)d_in[1];
    const float* sigma2 = (const float*)d_in[2];
    const float* sigma3 = (const float*)d_in[3];
    const float* eta    = (const float*)d_in[4];
    const float* lam    = (const float*)d_in[5];
    const float* mu     = (const float*)d_in[6];
    float* out = (float*)d_out;

    const int Tpt = 256;
    const int Bpt = (VOL + Tpt - 1) / Tpt;

    k_setup<<<1, 32>>>(sigma2, sigma3);
    k_init<<<Bpt, Tpt>>>(o, eta);

    dim3 blk(32, 8);
    dim3 grid1(3, 12, NSEG1 * CH);  // 576
    dim3 grid2(3, 12, NSEG2 * CH);  // 864
    dim3 grid4(3, 12, NSEG4);       // 288

    const int NB_ITERS = 10;
    for (int it = 0; it < NB_ITERS; ++it) {
        q1<<<grid1, blk>>>(I);
        q2<<<grid2, blk>>>();
        q3<<<grid2, blk>>>();
        q4<<<grid4, blk>>>(o, I, eta, lam, mu, out, (it == NB_ITERS - 1) ? 1 : 0);
    }
}

// round 6
// speedup vs baseline: 1.4317x; 1.0527x over previous
#include <cuda_runtime.h>

// Problem dims
#define ZD 96
#define YD 96
#define XD 96
#define PL 9216
#define VOL 884736
#define CH 4
#define KW 7

// Padded x-layout for intermediates: 4-float zero halo each side
#define XP 104
#define XOFF 4
#define PLP (YD * XP)          // 9984
#define VOLP (ZD * PLP)        // 958464

// Segment configs
#define SEG1 24
#define NSEG1 4
#define SEG2 16
#define NSEG2 6
#define SEG4 12
#define NSEG4 8

// ---------------- persistent device scratch ----------------
__device__ float g_wlif[CH][KW];
__device__ float g_wq[CH][KW];
__device__ float g_slif[CH][ZD];
__device__ float g_sq[CH][ZD];
__device__ int   g_same;
__device__ float g_u[CH * VOL];
__device__ float g_bufA[3 * CH * VOLP];  // padded
__device__ float g_bufB[3 * CH * VOLP];  // padded

// ---------------- zero the x-pad halos (once per launch) ----------------
__global__ void k_zeropad() {
    // pad cells: per padded row, x in [0,XOFF) U [XOFF+XD, XP)
    long nrows = (long)3 * CH * ZD * YD;
    long idx = (long)blockIdx.x * blockDim.x + threadIdx.x;
    long total = nrows * 8;   // 8 pad floats per row
    if (idx >= total) return;
    long row = idx >> 3;
    int p = (int)(idx & 7);
    int xo = (p < 4) ? p : (XOFF + XD + p - 4);
    g_bufA[row * XP + xo] = 0.f;
    g_bufB[row * XP + xo] = 0.f;
}

// ---------------- setup ----------------
__global__ void k_setup(const float* __restrict__ sigma2,
                        const float* __restrict__ sigma3) {
    int c = threadIdx.x;
    if (c == 0) {
        int s = 1;
        for (int k = 0; k < CH; k++) s &= (sigma2[k] == sigma3[k]);
        g_same = s;
    }
    if (c < CH) {
        float s2 = sigma2[c], s3 = sigma3[c];
        float w2[KW], w3[KW];
        float sum2 = 0.f, sum3 = 0.f;
        for (int t = 0; t < KW; t++) {
            float d = (float)(t - 3);
            w2[t] = expf(-d * d / (2.f * s2 * s2)); sum2 += w2[t];
            w3[t] = expf(-d * d / (2.f * s3 * s3)); sum3 += w3[t];
        }
        for (int t = 0; t < KW; t++) {
            g_wq[c][t]   = w2[t] / sum2;
            g_wlif[c][t] = w3[t] / sum3;
        }
        for (int p = 0; p < ZD; p++) {
            float sl = 0.f, sq = 0.f;
            for (int t = 0; t < KW; t++) {
                int q = p + t - 3;
                if (q >= 0 && q < ZD) { sl += g_wlif[c][t]; sq += g_wq[c][t]; }
            }
            g_slif[c][p] = sl;
            g_sq[c][p]   = sq;
        }
    }
}

// ---------------- u0 = softmax(o / eta) ----------------
__global__ void k_init(const float* __restrict__ o,
                       const float* __restrict__ eta_p) {
    int i = blockIdx.x * blockDim.x + threadIdx.x;
    if (i >= VOL) return;
    float inv_eta = 1.f / eta_p[0];
    float a0 = o[i] * inv_eta;
    float a1 = o[VOL + i] * inv_eta;
    float a2 = o[2 * VOL + i] * inv_eta;
    float a3 = o[3 * VOL + i] * inv_eta;
    float m = fmaxf(fmaxf(a0, a1), fmaxf(a2, a3));
    float e0 = expf(a0 - m), e1 = expf(a1 - m), e2 = expf(a2 - m), e3 = expf(a3 - m);
    float inv = 1.f / (e0 + e1 + e2 + e3);
    g_u[i] = e0 * inv;
    g_u[VOL + i] = e1 * inv;
    g_u[2 * VOL + i] = e2 * inv;
    g_u[3 * VOL + i] = e3 * inv;
}

// ============ q1: z-ring conv of {u*I, u} (+ wq(u) if sigmas differ) ============
// grid (3, 12, NSEG1*CH), block (32,8); thread fixed (x,y), walks z
__global__ __launch_bounds__(256) void q1(const float* __restrict__ I) {
    const int x = blockIdx.x * 32 + threadIdx.x;
    const int y = blockIdx.y * 8 + threadIdx.y;
    const int bz = blockIdx.z;
    const int c  = bz / NSEG1;
    const int zs = (bz - c * NSEG1) * SEG1;
    const int xy = y * XD + x;                 // unpadded read idx
    const int oxy = y * XP + x + XOFF;         // padded write idx
    const int same = g_same;

    float wl[KW], wq[KW];
#pragma unroll
    for (int t = 0; t < KW; t++) { wl[t] = g_wlif[c][t]; wq[t] = g_wq[c][t]; }

    const float* uC = g_u + c * VOL;
    float rI[KW], rU[KW];
#pragma unroll
    for (int t = 0; t < KW; t++) { rI[t] = 0.f; rU[t] = 0.f; }

#pragma unroll
    for (int k = 0; k < SEG1 + 6; ++k) {
        const int s = zs - 3 + k;
#pragma unroll
        for (int t = 0; t < KW - 1; t++) { rI[t] = rI[t + 1]; rU[t] = rU[t + 1]; }
        float uv = 0.f, Iv = 0.f;
        if (s >= 0 && s < ZD) { int gi = s * PL + xy; uv = uC[gi]; Iv = I[gi]; }
        rU[KW - 1] = uv;
        rI[KW - 1] = uv * Iv;
        if (k >= 6) {
            int z = s - 3;
            float a0 = 0.f, a1 = 0.f;
#pragma unroll
            for (int t = 0; t < KW; t++) { a0 += wl[t] * rI[t]; a1 += wl[t] * rU[t]; }
            int oidx = z * PLP + oxy;
            g_bufA[(0 * CH + c) * VOLP + oidx] = a0;
            g_bufA[(1 * CH + c) * VOLP + oidx] = a1;
            if (!same) {
                float a2 = 0.f;
#pragma unroll
                for (int t = 0; t < KW; t++) a2 += wq[t] * rU[t];
                g_bufA[(2 * CH + c) * VOLP + oidx] = a2;
            }
        }
    }
}

// ============ q2: y-ring + inline x-taps (padded, unconditional) -> Cn, Cn^2, C2q ============
// grid (3, 12, NSEG2*CH), block (32,8); thread fixed (x,z), walks y
__global__ __launch_bounds__(256) void q2() {
    const int x = blockIdx.x * 32 + threadIdx.x;
    const int z = blockIdx.y * 8 + threadIdx.y;
    const int bz = blockIdx.z;
    const int c  = bz / NSEG2;
    const int ys = (bz - c * NSEG2) * SEG2;
    const int zx = z * PLP + x + XOFF;
    const int same = g_same;

    float wl[KW], wq[KW];
#pragma unroll
    for (int t = 0; t < KW; t++) { wl[t] = g_wlif[c][t]; wq[t] = g_wq[c][t]; }

    const float* b0 = g_bufA + (0 * CH + c) * VOLP;
    const float* b1 = g_bufA + (1 * CH + c) * VOLP;
    const float* b2 = g_bufA + (2 * CH + c) * VOLP;

    float r0[KW], r1[KW], r2[KW];
#pragma unroll
    for (int t = 0; t < KW; t++) { r0[t] = 0.f; r1[t] = 0.f; r2[t] = 0.f; }

#pragma unroll
    for (int k = 0; k < SEG2 + 6; ++k) {
        const int s = ys - 3 + k;
#pragma unroll
        for (int t = 0; t < KW - 1; t++) { r0[t] = r0[t+1]; r1[t] = r1[t+1]; r2[t] = r2[t+1]; }
        float v0 = 0.f, v1 = 0.f, v2 = 0.f;
        if (s >= 0 && s < YD) {
            int base = zx + s * XP;
#pragma unroll
            for (int t = 0; t < KW; t++) {
                v0 += wl[t] * b0[base + t - 3];
                v1 += wl[t] * b1[base + t - 3];
            }
            if (!same) {
#pragma unroll
                for (int t = 0; t < KW; t++) v2 += wq[t] * b2[base + t - 3];
            }
        }
        r0[KW-1] = v0; r1[KW-1] = v1; r2[KW-1] = v2;
        if (k >= 6) {
            int y = s - 3;
            int oidx = zx + y * XP;
            float C1 = 0.f, C2 = 0.f;
#pragma unroll
            for (int t = 0; t < KW; t++) { C1 += wl[t] * r0[t]; C2 += wl[t] * r1[t]; }
            float C2q;
            if (!same) {
                C2q = 0.f;
#pragma unroll
                for (int t = 0; t < KW; t++) C2q += wq[t] * r2[t];
            } else {
                C2q = C2;
            }
            float Cn = (C1 + 1e-6f) / (C2 + 1e-6f);
            g_bufB[(0 * CH + c) * VOLP + oidx] = Cn;
            g_bufB[(1 * CH + c) * VOLP + oidx] = Cn * Cn;
            g_bufB[(2 * CH + c) * VOLP + oidx] = C2q;
        }
    }
}

// ============ q3: z-ring pointwise conv of {Cn, Cn^2} (padded in/out) ============
// grid (3, 12, NSEG2*CH), block (32,8); thread fixed (x,y), walks z
__global__ __launch_bounds__(256) void q3() {
    const int x = blockIdx.x * 32 + threadIdx.x;
    const int y = blockIdx.y * 8 + threadIdx.y;
    const int bz = blockIdx.z;
    const int c  = bz / NSEG2;
    const int zs = (bz - c * NSEG2) * SEG2;
    const int xy = y * XP + x + XOFF;

    float wl[KW];
#pragma unroll
    for (int t = 0; t < KW; t++) wl[t] = g_wlif[c][t];

    const float* b0 = g_bufB + (0 * CH + c) * VOLP;
    const float* b1 = g_bufB + (1 * CH + c) * VOLP;

    float r0[KW], r1[KW];
#pragma unroll
    for (int t = 0; t < KW; t++) { r0[t] = 0.f; r1[t] = 0.f; }

#pragma unroll
    for (int k = 0; k < SEG2 + 6; ++k) {
        const int s = zs - 3 + k;
#pragma unroll
        for (int t = 0; t < KW - 1; t++) { r0[t] = r0[t+1]; r1[t] = r1[t+1]; }
        float v0 = 0.f, v1 = 0.f;
        if (s >= 0 && s < ZD) { int gi = s * PLP + xy; v0 = b0[gi]; v1 = b1[gi]; }
        r0[KW-1] = v0; r1[KW-1] = v1;
        if (k >= 6) {
            int z = s - 3;
            float a0 = 0.f, a1 = 0.f;
#pragma unroll
            for (int t = 0; t < KW; t++) { a0 += wl[t] * r0[t]; a1 += wl[t] * r1[t]; }
            int oidx = z * PLP + xy;
            g_bufA[(0 * CH + c) * VOLP + oidx] = a0;
            g_bufA[(1 * CH + c) * VOLP + oidx] = a1;
        }
    }
}

// ============ q4: y-ring + x-taps (padded), ALL channels, Lif + q + softmax ============
// grid (3, 12, NSEG4), block (32,8); thread fixed (x,z), walks y
__global__ __launch_bounds__(256, 2) void q4(const float* __restrict__ o,
                                             const float* __restrict__ I,
                                             const float* __restrict__ eta_p,
                                             const float* __restrict__ lam_p,
                                             const float* __restrict__ mu_p,
                                             float* __restrict__ out,
                                             int write_ext) {
    const int x = blockIdx.x * 32 + threadIdx.x;
    const int z = blockIdx.y * 8 + threadIdx.y;
    const int ys = blockIdx.z * SEG4;
    const int zxp = z * PLP + x + XOFF;   // padded
    const int zxu = z * PL + x;           // unpadded

    const float lam = lam_p[0];
    const float mu  = mu_p[0];
    const float inv_eta = 1.f / eta_p[0];

    float wl[CH][KW];
#pragma unroll
    for (int c = 0; c < CH; c++)
#pragma unroll
        for (int t = 0; t < KW; t++) wl[c][t] = g_wlif[c][t];

    float slxz[CH], sqxz[CH];
#pragma unroll
    for (int c = 0; c < CH; c++) {
        slxz[c] = g_slif[c][x] * g_slif[c][z];
        sqxz[c] = g_sq[c][x] * g_sq[c][z];
    }

    float rE[CH][KW], rD[CH][KW];
#pragma unroll
    for (int c = 0; c < CH; c++)
#pragma unroll
        for (int t = 0; t < KW; t++) { rE[c][t] = 0.f; rD[c][t] = 0.f; }

    float* dst = write_ext ? out : g_u;

#pragma unroll
    for (int k = 0; k < SEG4 + 6; ++k) {
        const int s = ys - 3 + k;
#pragma unroll
        for (int c = 0; c < CH; c++)
#pragma unroll
            for (int t = 0; t < KW - 1; t++) { rE[c][t] = rE[c][t+1]; rD[c][t] = rD[c][t+1]; }

        if (s >= 0 && s < YD) {
            int base = zxp + s * XP;
#pragma unroll
            for (int c = 0; c < CH; c++) {
                const float* bE = g_bufA + (0 * CH + c) * VOLP;
                const float* bD = g_bufA + (1 * CH + c) * VOLP;
                float vE = 0.f, vD = 0.f;
#pragma unroll
                for (int t = 0; t < KW; t++) {
                    vE += wl[c][t] * bE[base + t - 3];
                    vD += wl[c][t] * bD[base + t - 3];
                }
                rE[c][KW-1] = vE; rD[c][KW-1] = vD;
            }
        } else {
#pragma unroll
            for (int c = 0; c < CH; c++) { rE[c][KW-1] = 0.f; rD[c][KW-1] = 0.f; }
        }

        if (k >= 6) {
            int y = s - 3;
            int iu = zxu + y * XD;      // unpadded
            int ip = zxp + y * XP;      // padded
            float Iv = I[iu];
            float a[CH];
#pragma unroll
            for (int c = 0; c < CH; c++) {
                float E = 0.f, D = 0.f;
#pragma unroll
                for (int t = 0; t < KW; t++) { E += wl[c][t] * rE[c][t]; D += wl[c][t] * rD[c][t]; }
                float cones = slxz[c] * g_slif[c][y];
                float Lif = D - 2.f * Iv * E + Iv * Iv * cones;
                float q = sqxz[c] * g_sq[c][y] - 2.f * g_bufB[(2 * CH + c) * VOLP + ip];
                a[c] = (o[c * VOL + iu] - mu * Lif - lam * q) * inv_eta;
            }
            float m = fmaxf(fmaxf(a[0], a[1]), fmaxf(a[2], a[3]));
            float e0 = expf(a[0] - m), e1 = expf(a[1] - m);
            float e2 = expf(a[2] - m), e3 = expf(a[3] - m);
            float inv = 1.f / (e0 + e1 + e2 + e3);
            dst[iu] = e0 * inv;
            dst[VOL + iu] = e1 * inv;
            dst[2 * VOL + iu] = e2 * inv;
            dst[3 * VOL + iu] = e3 * inv;
        }
    }
}

// ---------------- launch ----------------
extern "C" void kernel_launch(void* const* d_in, const int* in_sizes, int n_in,
                              void* d_out, int out_size) {
    const float* o      = (const float*)d_in[0];
    const float* I      = (const float*)d_in[1];
    const float* sigma2 = (const float*)d_in[2];
    const float* sigma3 = (const float*)d_in[3];
    const float* eta    = (const float*)d_in[4];
    const float* lam    = (const float*)d_in[5];
    const float* mu     = (const float*)d_in[6];
    float* out = (float*)d_out;

    const int Tpt = 256;
    const int Bpt = (VOL + Tpt - 1) / Tpt;

    k_setup<<<1, 32>>>(sigma2, sigma3);
    k_init<<<Bpt, Tpt>>>(o, eta);
    {
        long padtotal = (long)3 * CH * ZD * YD * 8;
        int zb = (int)((padtotal + 255) / 256);
        k_zeropad<<<zb, 256>>>();
    }

    dim3 blk(32, 8);
    dim3 grid1(3, 12, NSEG1 * CH);  // 576
    dim3 grid2(3, 12, NSEG2 * CH);  // 864
    dim3 grid4(3, 12, NSEG4);       // 288

    const int NB_ITERS = 10;
    for (int it = 0; it < NB_ITERS; ++it) {
        q1<<<grid1, blk>>>(I);
        q2<<<grid2, blk>>>();
        q3<<<grid2, blk>>>();
        q4<<<grid4, blk>>>(o, I, eta, lam, mu, out, (it == NB_ITERS - 1) ? 1 : 0);
    }
}

// round 7
// speedup vs baseline: 1.5452x; 1.0793x over previous
#include <cuda_runtime.h>

// Problem dims
#define ZD 96
#define YD 96
#define XD 96
#define PL 9216
#define VOL 884736
#define CH 4
#define KW 7

// Padded x-layout for intermediates: 4-float zero halo each side
#define XP 104
#define XOFF 4
#define PLP (YD * XP)          // 9984
#define VOLP (ZD * PLP)        // 958464

// Segment configs
#define SEG1 12
#define NSEG1 8
#define SEG2 12
#define NSEG2 8
#define SEG3 12
#define NSEG3 8
#define SEG4 8
#define NSEG4 12

// ---------------- persistent device scratch ----------------
__device__ float g_wlif[CH][KW];
__device__ float g_wq[CH][KW];
__device__ float g_slif[CH][ZD];
__device__ float g_sq[CH][ZD];
__device__ int   g_same;
__device__ float g_u[CH * VOL];
__device__ float g_bufA[3 * CH * VOLP];  // padded
__device__ float g_bufB[3 * CH * VOLP];  // padded

// ---------------- zero the x-pad halos (once per launch) ----------------
__global__ void k_zeropad() {
    long nrows = (long)3 * CH * ZD * YD;
    long idx = (long)blockIdx.x * blockDim.x + threadIdx.x;
    long total = nrows * 8;
    if (idx >= total) return;
    long row = idx >> 3;
    int p = (int)(idx & 7);
    int xo = (p < 4) ? p : (XOFF + XD + p - 4);
    g_bufA[row * XP + xo] = 0.f;
    g_bufB[row * XP + xo] = 0.f;
}

// ---------------- setup ----------------
__global__ void k_setup(const float* __restrict__ sigma2,
                        const float* __restrict__ sigma3) {
    int c = threadIdx.x;
    if (c == 0) {
        int s = 1;
        for (int k = 0; k < CH; k++) s &= (sigma2[k] == sigma3[k]);
        g_same = s;
    }
    if (c < CH) {
        float s2 = sigma2[c], s3 = sigma3[c];
        float w2[KW], w3[KW];
        float sum2 = 0.f, sum3 = 0.f;
        for (int t = 0; t < KW; t++) {
            float d = (float)(t - 3);
            w2[t] = expf(-d * d / (2.f * s2 * s2)); sum2 += w2[t];
            w3[t] = expf(-d * d / (2.f * s3 * s3)); sum3 += w3[t];
        }
        for (int t = 0; t < KW; t++) {
            g_wq[c][t]   = w2[t] / sum2;
            g_wlif[c][t] = w3[t] / sum3;
        }
        for (int p = 0; p < ZD; p++) {
            float sl = 0.f, sq = 0.f;
            for (int t = 0; t < KW; t++) {
                int q = p + t - 3;
                if (q >= 0 && q < ZD) { sl += g_wlif[c][t]; sq += g_wq[c][t]; }
            }
            g_slif[c][p] = sl;
            g_sq[c][p]   = sq;
        }
    }
}

// ---------------- u0 = softmax(o / eta) ----------------
__global__ void k_init(const float* __restrict__ o,
                       const float* __restrict__ eta_p) {
    int i = blockIdx.x * blockDim.x + threadIdx.x;
    if (i >= VOL) return;
    float inv_eta = 1.f / eta_p[0];
    float a0 = o[i] * inv_eta;
    float a1 = o[VOL + i] * inv_eta;
    float a2 = o[2 * VOL + i] * inv_eta;
    float a3 = o[3 * VOL + i] * inv_eta;
    float m = fmaxf(fmaxf(a0, a1), fmaxf(a2, a3));
    float e0 = expf(a0 - m), e1 = expf(a1 - m), e2 = expf(a2 - m), e3 = expf(a3 - m);
    float inv = 1.f / (e0 + e1 + e2 + e3);
    g_u[i] = e0 * inv;
    g_u[VOL + i] = e1 * inv;
    g_u[2 * VOL + i] = e2 * inv;
    g_u[3 * VOL + i] = e3 * inv;
}

__device__ __forceinline__ void f2fma(float w, float2 v, float2& acc) {
    acc.x += w * v.x; acc.y += w * v.y;
}

// ============ q1: z-ring conv of {u*I, u} — float2 (x-pair per thread) ============
// grid (3, 6, NSEG1*CH), block (16,16); thread fixed (x2,y), walks z
__global__ __launch_bounds__(256) void q1(const float* __restrict__ I) {
    const int x2 = blockIdx.x * 32 + threadIdx.x * 2;
    const int y  = blockIdx.y * 16 + threadIdx.y;
    const int bz = blockIdx.z;
    const int c  = bz / NSEG1;
    const int zs = (bz - c * NSEG1) * SEG1;
    const int xy  = y * XD + x2;
    const int oxy = y * XP + x2 + XOFF;
    const int same = g_same;

    float wl[KW], wq[KW];
#pragma unroll
    for (int t = 0; t < KW; t++) { wl[t] = g_wlif[c][t]; wq[t] = g_wq[c][t]; }

    const float* uC = g_u + c * VOL;
    float2 rI[KW], rU[KW];
#pragma unroll
    for (int t = 0; t < KW; t++) { rI[t] = make_float2(0.f, 0.f); rU[t] = rI[t]; }

#pragma unroll
    for (int k = 0; k < SEG1 + 6; ++k) {
        const int s = zs - 3 + k;
#pragma unroll
        for (int t = 0; t < KW - 1; t++) { rI[t] = rI[t + 1]; rU[t] = rU[t + 1]; }
        float2 uv = make_float2(0.f, 0.f), Iv = uv;
        if (s >= 0 && s < ZD) {
            int gi = s * PL + xy;
            uv = *reinterpret_cast<const float2*>(uC + gi);
            Iv = *reinterpret_cast<const float2*>(I + gi);
        }
        rU[KW - 1] = uv;
        rI[KW - 1] = make_float2(uv.x * Iv.x, uv.y * Iv.y);
        if (k >= 6) {
            int z = s - 3;
            float2 a0 = make_float2(0.f, 0.f), a1 = a0;
#pragma unroll
            for (int t = 0; t < KW; t++) { f2fma(wl[t], rI[t], a0); f2fma(wl[t], rU[t], a1); }
            int oidx = z * PLP + oxy;
            *reinterpret_cast<float2*>(g_bufA + (0 * CH + c) * VOLP + oidx) = a0;
            *reinterpret_cast<float2*>(g_bufA + (1 * CH + c) * VOLP + oidx) = a1;
            if (!same) {
                float2 a2 = make_float2(0.f, 0.f);
#pragma unroll
                for (int t = 0; t < KW; t++) f2fma(wq[t], rU[t], a2);
                *reinterpret_cast<float2*>(g_bufA + (2 * CH + c) * VOLP + oidx) = a2;
            }
        }
    }
}

// x-tap pair helper: 5 aligned float2 loads -> f[10]; even out: f[1..7], odd: f[2..8]
__device__ __forceinline__ float2 xtap_pair(const float* __restrict__ b, int bidx,
                                            const float* __restrict__ w) {
    float f[10];
    const float2* p = reinterpret_cast<const float2*>(b + bidx - 4);
#pragma unroll
    for (int j = 0; j < 5; j++) { float2 v = p[j]; f[2 * j] = v.x; f[2 * j + 1] = v.y; }
    float2 r = make_float2(0.f, 0.f);
#pragma unroll
    for (int t = 0; t < KW; t++) { r.x += w[t] * f[t + 1]; r.y += w[t] * f[t + 2]; }
    return r;
}

// ============ q2: y-ring + x-tap pairs -> Cn, Cn^2, C2q — float2 ============
// grid (3, 6, NSEG2*CH), block (16,16); thread fixed (x2,z), walks y
__global__ __launch_bounds__(256) void q2() {
    const int x2 = blockIdx.x * 32 + threadIdx.x * 2;
    const int z  = blockIdx.y * 16 + threadIdx.y;
    const int bz = blockIdx.z;
    const int c  = bz / NSEG2;
    const int ys = (bz - c * NSEG2) * SEG2;
    const int zx = z * PLP + x2 + XOFF;
    const int same = g_same;

    float wl[KW], wq[KW];
#pragma unroll
    for (int t = 0; t < KW; t++) { wl[t] = g_wlif[c][t]; wq[t] = g_wq[c][t]; }

    const float* b0 = g_bufA + (0 * CH + c) * VOLP;
    const float* b1 = g_bufA + (1 * CH + c) * VOLP;
    const float* b2 = g_bufA + (2 * CH + c) * VOLP;

    float2 r0[KW], r1[KW], r2[KW];
#pragma unroll
    for (int t = 0; t < KW; t++) { r0[t] = make_float2(0.f, 0.f); r1[t] = r0[t]; r2[t] = r0[t]; }

#pragma unroll
    for (int k = 0; k < SEG2 + 6; ++k) {
        const int s = ys - 3 + k;
#pragma unroll
        for (int t = 0; t < KW - 1; t++) { r0[t] = r0[t+1]; r1[t] = r1[t+1]; r2[t] = r2[t+1]; }
        float2 v0 = make_float2(0.f, 0.f), v1 = v0, v2 = v0;
        if (s >= 0 && s < YD) {
            int base = zx + s * XP;
            v0 = xtap_pair(b0, base, wl);
            v1 = xtap_pair(b1, base, wl);
            if (!same) v2 = xtap_pair(b2, base, wq);
        }
        r0[KW-1] = v0; r1[KW-1] = v1; r2[KW-1] = v2;
        if (k >= 6) {
            int y = s - 3;
            int oidx = zx + y * XP;
            float2 C1 = make_float2(0.f, 0.f), C2 = C1;
#pragma unroll
            for (int t = 0; t < KW; t++) { f2fma(wl[t], r0[t], C1); f2fma(wl[t], r1[t], C2); }
            float2 C2q;
            if (!same) {
                C2q = make_float2(0.f, 0.f);
#pragma unroll
                for (int t = 0; t < KW; t++) f2fma(wq[t], r2[t], C2q);
            } else {
                C2q = C2;
            }
            float2 Cn = make_float2((C1.x + 1e-6f) / (C2.x + 1e-6f),
                                    (C1.y + 1e-6f) / (C2.y + 1e-6f));
            *reinterpret_cast<float2*>(g_bufB + (0 * CH + c) * VOLP + oidx) = Cn;
            *reinterpret_cast<float2*>(g_bufB + (1 * CH + c) * VOLP + oidx) =
                make_float2(Cn.x * Cn.x, Cn.y * Cn.y);
            *reinterpret_cast<float2*>(g_bufB + (2 * CH + c) * VOLP + oidx) = C2q;
        }
    }
}

// ============ q3: z-ring pointwise conv of {Cn, Cn^2} — float2 ============
// grid (3, 6, NSEG3*CH), block (16,16); thread fixed (x2,y), walks z
__global__ __launch_bounds__(256) void q3() {
    const int x2 = blockIdx.x * 32 + threadIdx.x * 2;
    const int y  = blockIdx.y * 16 + threadIdx.y;
    const int bz = blockIdx.z;
    const int c  = bz / NSEG3;
    const int zs = (bz - c * NSEG3) * SEG3;
    const int xy = y * XP + x2 + XOFF;

    float wl[KW];
#pragma unroll
    for (int t = 0; t < KW; t++) wl[t] = g_wlif[c][t];

    const float* b0 = g_bufB + (0 * CH + c) * VOLP;
    const float* b1 = g_bufB + (1 * CH + c) * VOLP;

    float2 r0[KW], r1[KW];
#pragma unroll
    for (int t = 0; t < KW; t++) { r0[t] = make_float2(0.f, 0.f); r1[t] = r0[t]; }

#pragma unroll
    for (int k = 0; k < SEG3 + 6; ++k) {
        const int s = zs - 3 + k;
#pragma unroll
        for (int t = 0; t < KW - 1; t++) { r0[t] = r0[t+1]; r1[t] = r1[t+1]; }
        float2 v0 = make_float2(0.f, 0.f), v1 = v0;
        if (s >= 0 && s < ZD) {
            int gi = s * PLP + xy;
            v0 = *reinterpret_cast<const float2*>(b0 + gi);
            v1 = *reinterpret_cast<const float2*>(b1 + gi);
        }
        r0[KW-1] = v0; r1[KW-1] = v1;
        if (k >= 6) {
            int z = s - 3;
            float2 a0 = make_float2(0.f, 0.f), a1 = a0;
#pragma unroll
            for (int t = 0; t < KW; t++) { f2fma(wl[t], r0[t], a0); f2fma(wl[t], r1[t], a1); }
            int oidx = z * PLP + xy;
            *reinterpret_cast<float2*>(g_bufA + (0 * CH + c) * VOLP + oidx) = a0;
            *reinterpret_cast<float2*>(g_bufA + (1 * CH + c) * VOLP + oidx) = a1;
        }
    }
}

// ============ q4: y-ring + x-taps, ALL channels, Lif + q + softmax (scalar) ============
// grid (3, 12, NSEG4), block (32,8); thread fixed (x,z), walks y
__global__ __launch_bounds__(256) void q4(const float* __restrict__ o,
                                          const float* __restrict__ I,
                                          const float* __restrict__ eta_p,
                                          const float* __restrict__ lam_p,
                                          const float* __restrict__ mu_p,
                                          float* __restrict__ out,
                                          int write_ext) {
    const int x = blockIdx.x * 32 + threadIdx.x;
    const int z = blockIdx.y * 8 + threadIdx.y;
    const int ys = blockIdx.z * SEG4;
    const int zxp = z * PLP + x + XOFF;
    const int zxu = z * PL + x;

    const float lam = lam_p[0];
    const float mu  = mu_p[0];
    const float inv_eta = 1.f / eta_p[0];

    float wl[CH][KW];
#pragma unroll
    for (int c = 0; c < CH; c++)
#pragma unroll
        for (int t = 0; t < KW; t++) wl[c][t] = g_wlif[c][t];

    float slxz[CH], sqxz[CH];
#pragma unroll
    for (int c = 0; c < CH; c++) {
        slxz[c] = g_slif[c][x] * g_slif[c][z];
        sqxz[c] = g_sq[c][x] * g_sq[c][z];
    }

    float rE[CH][KW], rD[CH][KW];
#pragma unroll
    for (int c = 0; c < CH; c++)
#pragma unroll
        for (int t = 0; t < KW; t++) { rE[c][t] = 0.f; rD[c][t] = 0.f; }

    float* dst = write_ext ? out : g_u;

#pragma unroll
    for (int k = 0; k < SEG4 + 6; ++k) {
        const int s = ys - 3 + k;
#pragma unroll
        for (int c = 0; c < CH; c++)
#pragma unroll
            for (int t = 0; t < KW - 1; t++) { rE[c][t] = rE[c][t+1]; rD[c][t] = rD[c][t+1]; }

        if (s >= 0 && s < YD) {
            int base = zxp + s * XP;
#pragma unroll
            for (int c = 0; c < CH; c++) {
                const float* bE = g_bufA + (0 * CH + c) * VOLP;
                const float* bD = g_bufA + (1 * CH + c) * VOLP;
                float vE = 0.f, vD = 0.f;
#pragma unroll
                for (int t = 0; t < KW; t++) {
                    vE += wl[c][t] * bE[base + t - 3];
                    vD += wl[c][t] * bD[base + t - 3];
                }
                rE[c][KW-1] = vE; rD[c][KW-1] = vD;
            }
        } else {
#pragma unroll
            for (int c = 0; c < CH; c++) { rE[c][KW-1] = 0.f; rD[c][KW-1] = 0.f; }
        }

        if (k >= 6) {
            int y = s - 3;
            int iu = zxu + y * XD;
            int ip = zxp + y * XP;
            float Iv = I[iu];
            float a[CH];
#pragma unroll
            for (int c = 0; c < CH; c++) {
                float E = 0.f, D = 0.f;
#pragma unroll
                for (int t = 0; t < KW; t++) { E += wl[c][t] * rE[c][t]; D += wl[c][t] * rD[c][t]; }
                float cones = slxz[c] * g_slif[c][y];
                float Lif = D - 2.f * Iv * E + Iv * Iv * cones;
                float q = sqxz[c] * g_sq[c][y] - 2.f * g_bufB[(2 * CH + c) * VOLP + ip];
                a[c] = (o[c * VOL + iu] - mu * Lif - lam * q) * inv_eta;
            }
            float m = fmaxf(fmaxf(a[0], a[1]), fmaxf(a[2], a[3]));
            float e0 = expf(a[0] - m), e1 = expf(a[1] - m);
            float e2 = expf(a[2] - m), e3 = expf(a[3] - m);
            float inv = 1.f / (e0 + e1 + e2 + e3);
            dst[iu] = e0 * inv;
            dst[VOL + iu] = e1 * inv;
            dst[2 * VOL + iu] = e2 * inv;
            dst[3 * VOL + iu] = e3 * inv;
        }
    }
}

// ---------------- launch ----------------
extern "C" void kernel_launch(void* const* d_in, const int* in_sizes, int n_in,
                              void* d_out, int out_size) {
    const float* o      = (const float*)d_in[0];
    const float* I      = (const float*)d_in[1];
    const float* sigma2 = (const float*)d_in[2];
    const float* sigma3 = (const float*)d_in[3];
    const float* eta    = (const float*)d_in[4];
    const float* lam    = (const float*)d_in[5];
    const float* mu     = (const float*)d_in[6];
    float* out = (float*)d_out;

    const int Tpt = 256;
    const int Bpt = (VOL + Tpt - 1) / Tpt;

    k_setup<<<1, 32>>>(sigma2, sigma3);
    k_init<<<Bpt, Tpt>>>(o, eta);
    {
        long padtotal = (long)3 * CH * ZD * YD * 8;
        int zb = (int)((padtotal + 255) / 256);
        k_zeropad<<<zb, 256>>>();
    }

    dim3 blkV(16, 16);
    dim3 blkS(32, 8);
    dim3 grid1(3, 6, NSEG1 * CH);   // 576
    dim3 grid2(3, 6, NSEG2 * CH);   // 576
    dim3 grid3(3, 6, NSEG3 * CH);   // 576
    dim3 grid4(3, 12, NSEG4);       // 432

    const int NB_ITERS = 10;
    for (int it = 0; it < NB_ITERS; ++it) {
        q1<<<grid1, blkV>>>(I);
        q2<<<grid2, blkV>>>();
        q3<<<grid3, blkV>>>();
        q4<<<grid4, blkS>>>(o, I, eta, lam, mu, out, (it == NB_ITERS - 1) ? 1 : 0);
    }
}

// round 8
// speedup vs baseline: 1.6829x; 1.0891x over previous
#include <cuda_runtime.h>

// Problem dims
#define ZD 96
#define YD 96
#define XD 96
#define PL 9216
#define VOL 884736
#define CH 4
#define KW 7

// Padded x-layout for intermediates
#define XP 104
#define XOFF 4
#define PLP (YD * XP)
#define VOLP (ZD * PLP)

// Segment configs
#define SEG1 6
#define NSEG1 16
#define SEG2 8
#define NSEG2 12
#define SEG3 6
#define NSEG3 16
#define SEG4 6
#define NSEG4 16

// ---------------- persistent device scratch ----------------
__device__ float g_wlif[CH][KW];
__device__ float g_wq[CH][KW];
__device__ float g_slif[CH][ZD];
__device__ float g_sq[CH][ZD];
__device__ int   g_same;
__device__ float g_u[CH * VOL];
__device__ float g_bufA[3 * CH * VOLP];
__device__ float g_bufB[3 * CH * VOLP];

// ---------------- zero the x-pad halos ----------------
__global__ void k_zeropad() {
    long nrows = (long)3 * CH * ZD * YD;
    long idx = (long)blockIdx.x * blockDim.x + threadIdx.x;
    long total = nrows * 8;
    if (idx >= total) return;
    long row = idx >> 3;
    int p = (int)(idx & 7);
    int xo = (p < 4) ? p : (XOFF + XD + p - 4);
    g_bufA[row * XP + xo] = 0.f;
    g_bufB[row * XP + xo] = 0.f;
}

// ---------------- setup ----------------
__global__ void k_setup(const float* __restrict__ sigma2,
                        const float* __restrict__ sigma3) {
    int c = threadIdx.x;
    if (c == 0) {
        int s = 1;
        for (int k = 0; k < CH; k++) s &= (sigma2[k] == sigma3[k]);
        g_same = s;
    }
    if (c < CH) {
        float s2 = sigma2[c], s3 = sigma3[c];
        float w2[KW], w3[KW];
        float sum2 = 0.f, sum3 = 0.f;
        for (int t = 0; t < KW; t++) {
            float d = (float)(t - 3);
            w2[t] = expf(-d * d / (2.f * s2 * s2)); sum2 += w2[t];
            w3[t] = expf(-d * d / (2.f * s3 * s3)); sum3 += w3[t];
        }
        for (int t = 0; t < KW; t++) {
            g_wq[c][t]   = w2[t] / sum2;
            g_wlif[c][t] = w3[t] / sum3;
        }
        for (int p = 0; p < ZD; p++) {
            float sl = 0.f, sq = 0.f;
            for (int t = 0; t < KW; t++) {
                int q = p + t - 3;
                if (q >= 0 && q < ZD) { sl += g_wlif[c][t]; sq += g_wq[c][t]; }
            }
            g_slif[c][p] = sl;
            g_sq[c][p]   = sq;
        }
    }
}

// ---------------- u0 = softmax(o / eta) ----------------
__global__ void k_init(const float* __restrict__ o,
                       const float* __restrict__ eta_p) {
    int i = blockIdx.x * blockDim.x + threadIdx.x;
    if (i >= VOL) return;
    float inv_eta = 1.f / eta_p[0];
    float a0 = o[i] * inv_eta;
    float a1 = o[VOL + i] * inv_eta;
    float a2 = o[2 * VOL + i] * inv_eta;
    float a3 = o[3 * VOL + i] * inv_eta;
    float m = fmaxf(fmaxf(a0, a1), fmaxf(a2, a3));
    float e0 = expf(a0 - m), e1 = expf(a1 - m), e2 = expf(a2 - m), e3 = expf(a3 - m);
    float inv = 1.f / (e0 + e1 + e2 + e3);
    g_u[i] = e0 * inv;
    g_u[VOL + i] = e1 * inv;
    g_u[2 * VOL + i] = e2 * inv;
    g_u[3 * VOL + i] = e3 * inv;
}

__device__ __forceinline__ void f2fma(float w, float2 v, float2& acc) {
    acc.x += w * v.x; acc.y += w * v.y;
}

// ============ q1: z-ring conv of {u*I, u} — float2, templated on SAME ============
template <bool SAME>
__device__ __forceinline__ void q1_body(const float* __restrict__ I,
                                        int c, int zs, int xy, int oxy) {
    float wl[KW], wq[KW];
#pragma unroll
    for (int t = 0; t < KW; t++) { wl[t] = g_wlif[c][t]; if (!SAME) wq[t] = g_wq[c][t]; }

    const float* uC = g_u + c * VOL;
    float2 rI[KW], rU[KW], rQ[KW];
#pragma unroll
    for (int t = 0; t < KW; t++) {
        rI[t] = make_float2(0.f, 0.f); rU[t] = rI[t];
        if (!SAME) rQ[t] = rI[t];
    }

#pragma unroll
    for (int k = 0; k < SEG1 + 6; ++k) {
        const int s = zs - 3 + k;
#pragma unroll
        for (int t = 0; t < KW - 1; t++) {
            rI[t] = rI[t + 1]; rU[t] = rU[t + 1];
            if (!SAME) rQ[t] = rQ[t + 1];
        }
        float2 uv = make_float2(0.f, 0.f), Iv = uv;
        if (s >= 0 && s < ZD) {
            int gi = s * PL + xy;
            uv = *reinterpret_cast<const float2*>(uC + gi);
            Iv = *reinterpret_cast<const float2*>(I + gi);
        }
        rU[KW - 1] = uv;
        rI[KW - 1] = make_float2(uv.x * Iv.x, uv.y * Iv.y);
        if (!SAME) rQ[KW - 1] = uv;
        if (k >= 6) {
            int z = s - 3;
            float2 a0 = make_float2(0.f, 0.f), a1 = a0;
#pragma unroll
            for (int t = 0; t < KW; t++) { f2fma(wl[t], rI[t], a0); f2fma(wl[t], rU[t], a1); }
            int oidx = z * PLP + oxy;
            *reinterpret_cast<float2*>(g_bufA + (0 * CH + c) * VOLP + oidx) = a0;
            *reinterpret_cast<float2*>(g_bufA + (1 * CH + c) * VOLP + oidx) = a1;
            if (!SAME) {
                float2 a2 = make_float2(0.f, 0.f);
#pragma unroll
                for (int t = 0; t < KW; t++) f2fma(wq[t], rQ[t], a2);
                *reinterpret_cast<float2*>(g_bufA + (2 * CH + c) * VOLP + oidx) = a2;
            }
        }
    }
}

__global__ __launch_bounds__(256) void q1(const float* __restrict__ I) {
    const int x2 = blockIdx.x * 32 + threadIdx.x * 2;
    const int y  = blockIdx.y * 16 + threadIdx.y;
    const int bz = blockIdx.z;
    const int c  = bz / NSEG1;
    const int zs = (bz - c * NSEG1) * SEG1;
    const int xy  = y * XD + x2;
    const int oxy = y * XP + x2 + XOFF;
    if (g_same) q1_body<true>(I, c, zs, xy, oxy);
    else        q1_body<false>(I, c, zs, xy, oxy);
}

// x-tap pair: 5 aligned float2 loads
__device__ __forceinline__ float2 xtap_pair(const float* __restrict__ b, int bidx,
                                            const float* __restrict__ w) {
    float f[10];
    const float2* p = reinterpret_cast<const float2*>(b + bidx - 4);
#pragma unroll
    for (int j = 0; j < 5; j++) { float2 v = p[j]; f[2 * j] = v.x; f[2 * j + 1] = v.y; }
    float2 r = make_float2(0.f, 0.f);
#pragma unroll
    for (int t = 0; t < KW; t++) { r.x += w[t] * f[t + 1]; r.y += w[t] * f[t + 2]; }
    return r;
}

// ============ q2: y-ring + x-tap pairs -> Cn, Cn^2, C2q — templated ============
template <bool SAME>
__device__ __forceinline__ void q2_body(int c, int ys, int zx) {
    float wl[KW], wq[KW];
#pragma unroll
    for (int t = 0; t < KW; t++) { wl[t] = g_wlif[c][t]; if (!SAME) wq[t] = g_wq[c][t]; }

    const float* b0 = g_bufA + (0 * CH + c) * VOLP;
    const float* b1 = g_bufA + (1 * CH + c) * VOLP;
    const float* b2 = g_bufA + (2 * CH + c) * VOLP;

    float2 r0[KW], r1[KW], r2[KW];
#pragma unroll
    for (int t = 0; t < KW; t++) {
        r0[t] = make_float2(0.f, 0.f); r1[t] = r0[t];
        if (!SAME) r2[t] = r0[t];
    }

#pragma unroll
    for (int k = 0; k < SEG2 + 6; ++k) {
        const int s = ys - 3 + k;
#pragma unroll
        for (int t = 0; t < KW - 1; t++) {
            r0[t] = r0[t+1]; r1[t] = r1[t+1];
            if (!SAME) r2[t] = r2[t+1];
        }
        float2 v0 = make_float2(0.f, 0.f), v1 = v0, v2 = v0;
        if (s >= 0 && s < YD) {
            int base = zx + s * XP;
            v0 = xtap_pair(b0, base, wl);
            v1 = xtap_pair(b1, base, wl);
            if (!SAME) v2 = xtap_pair(b2, base, wq);
        }
        r0[KW-1] = v0; r1[KW-1] = v1;
        if (!SAME) r2[KW-1] = v2;
        if (k >= 6) {
            int y = s - 3;
            int oidx = zx + y * XP;
            float2 C1 = make_float2(0.f, 0.f), C2 = C1;
#pragma unroll
            for (int t = 0; t < KW; t++) { f2fma(wl[t], r0[t], C1); f2fma(wl[t], r1[t], C2); }
            float2 C2q;
            if (!SAME) {
                C2q = make_float2(0.f, 0.f);
#pragma unroll
                for (int t = 0; t < KW; t++) f2fma(wq[t], r2[t], C2q);
            } else {
                C2q = C2;
            }
            float2 Cn = make_float2((C1.x + 1e-6f) / (C2.x + 1e-6f),
                                    (C1.y + 1e-6f) / (C2.y + 1e-6f));
            *reinterpret_cast<float2*>(g_bufB + (0 * CH + c) * VOLP + oidx) = Cn;
            *reinterpret_cast<float2*>(g_bufB + (1 * CH + c) * VOLP + oidx) =
                make_float2(Cn.x * Cn.x, Cn.y * Cn.y);
            *reinterpret_cast<float2*>(g_bufB + (2 * CH + c) * VOLP + oidx) = C2q;
        }
    }
}

__global__ __launch_bounds__(256) void q2() {
    const int x2 = blockIdx.x * 32 + threadIdx.x * 2;
    const int z  = blockIdx.y * 16 + threadIdx.y;
    const int bz = blockIdx.z;
    const int c  = bz / NSEG2;
    const int ys = (bz - c * NSEG2) * SEG2;
    const int zx = z * PLP + x2 + XOFF;
    if (g_same) q2_body<true>(c, ys, zx);
    else        q2_body<false>(c, ys, zx);
}

// ============ q3: z-ring pointwise conv of {Cn, Cn^2} — float2 ============
__global__ __launch_bounds__(256) void q3() {
    const int x2 = blockIdx.x * 32 + threadIdx.x * 2;
    const int y  = blockIdx.y * 16 + threadIdx.y;
    const int bz = blockIdx.z;
    const int c  = bz / NSEG3;
    const int zs = (bz - c * NSEG3) * SEG3;
    const int xy = y * XP + x2 + XOFF;

    float wl[KW];
#pragma unroll
    for (int t = 0; t < KW; t++) wl[t] = g_wlif[c][t];

    const float* b0 = g_bufB + (0 * CH + c) * VOLP;
    const float* b1 = g_bufB + (1 * CH + c) * VOLP;

    float2 r0[KW], r1[KW];
#pragma unroll
    for (int t = 0; t < KW; t++) { r0[t] = make_float2(0.f, 0.f); r1[t] = r0[t]; }

#pragma unroll
    for (int k = 0; k < SEG3 + 6; ++k) {
        const int s = zs - 3 + k;
#pragma unroll
        for (int t = 0; t < KW - 1; t++) { r0[t] = r0[t+1]; r1[t] = r1[t+1]; }
        float2 v0 = make_float2(0.f, 0.f), v1 = v0;
        if (s >= 0 && s < ZD) {
            int gi = s * PLP + xy;
            v0 = *reinterpret_cast<const float2*>(b0 + gi);
            v1 = *reinterpret_cast<const float2*>(b1 + gi);
        }
        r0[KW-1] = v0; r1[KW-1] = v1;
        if (k >= 6) {
            int z = s - 3;
            float2 a0 = make_float2(0.f, 0.f), a1 = a0;
#pragma unroll
            for (int t = 0; t < KW; t++) { f2fma(wl[t], r0[t], a0); f2fma(wl[t], r1[t], a1); }
            int oidx = z * PLP + xy;
            *reinterpret_cast<float2*>(g_bufA + (0 * CH + c) * VOLP + oidx) = a0;
            *reinterpret_cast<float2*>(g_bufA + (1 * CH + c) * VOLP + oidx) = a1;
        }
    }
}

// ============ q4: y-ring + x-taps, ALL channels, Lif + q + softmax ============
// weights in smem to cut registers
__global__ __launch_bounds__(256) void q4(const float* __restrict__ o,
                                          const float* __restrict__ I,
                                          const float* __restrict__ eta_p,
                                          const float* __restrict__ lam_p,
                                          const float* __restrict__ mu_p,
                                          float* __restrict__ out,
                                          int write_ext) {
    const int x = blockIdx.x * 32 + threadIdx.x;
    const int z = blockIdx.y * 8 + threadIdx.y;
    const int ys = blockIdx.z * SEG4;
    const int zxp = z * PLP + x + XOFF;
    const int zxu = z * PL + x;

    __shared__ float swl[CH][KW];
    {
        int tid = threadIdx.y * 32 + threadIdx.x;
        if (tid < CH * KW) ((float*)swl)[tid] = ((const float*)g_wlif)[tid];
    }
    __syncthreads();

    const float lam = lam_p[0];
    const float mu  = mu_p[0];
    const float inv_eta = 1.f / eta_p[0];

    float slxz[CH], sqxz[CH];
#pragma unroll
    for (int c = 0; c < CH; c++) {
        slxz[c] = g_slif[c][x] * g_slif[c][z];
        sqxz[c] = g_sq[c][x] * g_sq[c][z];
    }

    float rE[CH][KW], rD[CH][KW];
#pragma unroll
    for (int c = 0; c < CH; c++)
#pragma unroll
        for (int t = 0; t < KW; t++) { rE[c][t] = 0.f; rD[c][t] = 0.f; }

    float* dst = write_ext ? out : g_u;

#pragma unroll
    for (int k = 0; k < SEG4 + 6; ++k) {
        const int s = ys - 3 + k;
#pragma unroll
        for (int c = 0; c < CH; c++)
#pragma unroll
            for (int t = 0; t < KW - 1; t++) { rE[c][t] = rE[c][t+1]; rD[c][t] = rD[c][t+1]; }

        if (s >= 0 && s < YD) {
            int base = zxp + s * XP;
#pragma unroll
            for (int c = 0; c < CH; c++) {
                const float* bE = g_bufA + (0 * CH + c) * VOLP;
                const float* bD = g_bufA + (1 * CH + c) * VOLP;
                float vE = 0.f, vD = 0.f;
#pragma unroll
                for (int t = 0; t < KW; t++) {
                    float w = swl[c][t];
                    vE += w * bE[base + t - 3];
                    vD += w * bD[base + t - 3];
                }
                rE[c][KW-1] = vE; rD[c][KW-1] = vD;
            }
        } else {
#pragma unroll
            for (int c = 0; c < CH; c++) { rE[c][KW-1] = 0.f; rD[c][KW-1] = 0.f; }
        }

        if (k >= 6) {
            int y = s - 3;
            int iu = zxu + y * XD;
            int ip = zxp + y * XP;
            float Iv = I[iu];
            float a[CH];
#pragma unroll
            for (int c = 0; c < CH; c++) {
                float E = 0.f, D = 0.f;
#pragma unroll
                for (int t = 0; t < KW; t++) {
                    float w = swl[c][t];
                    E += w * rE[c][t]; D += w * rD[c][t];
                }
                float cones = slxz[c] * g_slif[c][y];
                float Lif = D - 2.f * Iv * E + Iv * Iv * cones;
                float q = sqxz[c] * g_sq[c][y] - 2.f * g_bufB[(2 * CH + c) * VOLP + ip];
                a[c] = (o[c * VOL + iu] - mu * Lif - lam * q) * inv_eta;
            }
            float m = fmaxf(fmaxf(a[0], a[1]), fmaxf(a[2], a[3]));
            float e0 = expf(a[0] - m), e1 = expf(a[1] - m);
            float e2 = expf(a[2] - m), e3 = expf(a[3] - m);
            float inv = 1.f / (e0 + e1 + e2 + e3);
            dst[iu] = e0 * inv;
            dst[VOL + iu] = e1 * inv;
            dst[2 * VOL + iu] = e2 * inv;
            dst[3 * VOL + iu] = e3 * inv;
        }
    }
}

// ---------------- launch ----------------
extern "C" void kernel_launch(void* const* d_in, const int* in_sizes, int n_in,
                              void* d_out, int out_size) {
    const float* o      = (const float*)d_in[0];
    const float* I      = (const float*)d_in[1];
    const float* sigma2 = (const float*)d_in[2];
    const float* sigma3 = (const float*)d_in[3];
    const float* eta    = (const float*)d_in[4];
    const float* lam    = (const float*)d_in[5];
    const float* mu     = (const float*)d_in[6];
    float* out = (float*)d_out;

    const int Tpt = 256;
    const int Bpt = (VOL + Tpt - 1) / Tpt;

    k_setup<<<1, 32>>>(sigma2, sigma3);
    k_init<<<Bpt, Tpt>>>(o, eta);
    {
        long padtotal = (long)3 * CH * ZD * YD * 8;
        int zb = (int)((padtotal + 255) / 256);
        k_zeropad<<<zb, 256>>>();
    }

    dim3 blkV(16, 16);
    dim3 blkS(32, 8);
    dim3 grid1(3, 6, NSEG1 * CH);   // 1152
    dim3 grid2(3, 6, NSEG2 * CH);   // 864
    dim3 grid3(3, 6, NSEG3 * CH);   // 1152
    dim3 grid4(3, 12, NSEG4);       // 576

    const int NB_ITERS = 10;
    for (int it = 0; it < NB_ITERS; ++it) {
        q1<<<grid1, blkV>>>(I);
        q2<<<grid2, blkV>>>();
        q3<<<grid3, blkV>>>();
        q4<<<grid4, blkS>>>(o, I, eta, lam, mu, out, (it == NB_ITERS - 1) ? 1 : 0);
    }
}